// round 2
// baseline (speedup 1.0000x reference)
#include <cuda_runtime.h>

#define IMG_W    512
#define OUTW     502
#define NPLANE   48
#define IN_COLS  128
#define OUT_COLS 118
#define OUT_ROWS 32
#define IN_ROWS  42      // OUT_ROWS + 10
#define PITCH    129     // odd -> conflict-free strided smem reads
#define KS       11

typedef unsigned long long u64;

__device__ double g_acc;

// Gaussian(sigma=1.5, k=11) normalized weights (exact to ~1e-7)
static __device__ constexpr float WT[KS] = {
    0.00102838f, 0.00759876f, 0.03600077f, 0.10936069f, 0.21300554f,
    0.26601172f,
    0.21300554f, 0.10936069f, 0.03600077f, 0.00759876f, 0.00102838f
};

__device__ __forceinline__ u64 pack2(float lo, float hi) {
    u64 r; asm("mov.b64 %0,{%1,%2};" : "=l"(r) : "f"(lo), "f"(hi)); return r;
}
__device__ __forceinline__ void unpack2(u64 v, float& lo, float& hi) {
    asm("mov.b64 {%0,%1},%2;" : "=f"(lo), "=f"(hi) : "l"(v));
}
__device__ __forceinline__ u64 fma2(u64 a, u64 b, u64 c) {
    u64 r; asm("fma.rn.f32x2 %0,%1,%2,%3;" : "=l"(r) : "l"(a), "l"(b), "l"(c)); return r;
}
__device__ __forceinline__ u64 mul2(u64 a, u64 b) {
    u64 r; asm("mul.rn.f32x2 %0,%1,%2;" : "=l"(r) : "l"(a), "l"(b)); return r;
}

__global__ void zero_acc_kernel() { g_acc = 0.0; }

__global__ void finalize_kernel(float* out) {
    const double n = (double)NPLANE * (double)OUTW * (double)OUTW;
    out[0] = (float)(1.0 - g_acc / n);
}

extern __shared__ unsigned char smem_raw[];

__launch_bounds__(128)
__global__ void ssim_kernel(const float* __restrict__ X, const float* __restrict__ Y) {
    u64*   buf01 = (u64*)smem_raw;                         // (mu_x, mu_y) pre-horizontal
    u64*   buf23 = buf01 + OUT_ROWS * PITCH;               // (E[x2], E[y2])
    float* buf4  = (float*)(buf23 + OUT_ROWS * PITCH);     // E[xy]

    const int tid   = threadIdx.x;
    const int plane = blockIdx.z;
    const int c0    = blockIdx.x * OUT_COLS;
    const int r0    = blockIdx.y * OUT_ROWS;

    const float* __restrict__ xp = X + (size_t)plane * IMG_W * IMG_W;
    const float* __restrict__ yp = Y + (size_t)plane * IMG_W * IMG_W;

    u64 wp[KS];
    #pragma unroll
    for (int k = 0; k < KS; k++) wp[k] = pack2(WT[k], WT[k]);

    // ================= Pass 1: vertical rolling blur (lane = column) =================
    {
        const int  c     = tid;
        const int  gc    = c0 + c;
        const bool colok = gc < IMG_W;
        const float* __restrict__ xcol = xp + gc;
        const float* __restrict__ ycol = yp + gc;

        // 11-deep row prefetch pipeline
        float px[KS], py[KS];
        #pragma unroll
        for (int i = 0; i < KS; i++) {
            int  gr = r0 + i;
            bool ok = colok && (gr < IMG_W);
            px[i] = ok ? __ldg(xcol + gr * IMG_W) : 0.f;
            py[i] = ok ? __ldg(ycol + gr * IMG_W) : 0.f;
        }

        u64 a01[KS], a23[KS]; float a4[KS];
        #pragma unroll
        for (int s = 0; s < KS; s++) { a01[s] = 0ull; a23[s] = 0ull; a4[s] = 0.f; }

        // ---- warmup rows i = 0..10 ----
        #pragma unroll
        for (int i = 0; i < KS; i++) {
            float vx = px[i], vy = py[i];
            {   // prefetch row i+11 into same slot
                int nr = i + KS;
                if (nr < IN_ROWS) {
                    int  gr = r0 + nr;
                    bool ok = colok && (gr < IMG_W);
                    px[i] = ok ? __ldg(xcol + gr * IMG_W) : 0.f;
                    py[i] = ok ? __ldg(ycol + gr * IMG_W) : 0.f;
                }
            }
            u64   v01 = pack2(vx, vy);
            u64   v23 = mul2(v01, v01);
            float v4  = vx * vy;
            #pragma unroll
            for (int k = 0; k <= i; k++) {
                int d = (i - k) % KS;
                a01[d] = fma2(wp[k], v01, a01[d]);
                a23[d] = fma2(wp[k], v23, a23[d]);
                a4[d]  = fmaf(WT[k], v4, a4[d]);
            }
            if (i == KS - 1) {   // emit v-row 0 (slot 0)
                buf01[c] = a01[0];
                buf23[c] = a23[0];
                buf4 [c] = a4[0];
                a01[0] = 0ull; a23[0] = 0ull; a4[0] = 0.f;
            }
        }

        // ---- steady rows i = 11..41 ----
        for (int base = KS; base < 44; base += KS) {
            #pragma unroll
            for (int ii = 0; ii < KS; ii++) {
                int i = base + ii;
                if (i < IN_ROWS) {
                    float vx = px[ii], vy = py[ii];
                    {
                        int nr = i + KS;
                        if (nr < IN_ROWS) {
                            int  gr = r0 + nr;
                            bool ok = colok && (gr < IMG_W);
                            px[ii] = ok ? __ldg(xcol + gr * IMG_W) : 0.f;
                            py[ii] = ok ? __ldg(ycol + gr * IMG_W) : 0.f;
                        }
                    }
                    u64   v01 = pack2(vx, vy);
                    u64   v23 = mul2(v01, v01);
                    float v4  = vx * vy;
                    #pragma unroll
                    for (int k = 0; k < KS; k++) {
                        int d = (ii - k + KS) % KS;
                        a01[d] = fma2(wp[k], v01, a01[d]);
                        a23[d] = fma2(wp[k], v23, a23[d]);
                        a4[d]  = fmaf(WT[k], v4, a4[d]);
                    }
                    int e = (ii + 1) % KS;
                    int j = i - (KS - 1);
                    buf01[j * PITCH + c] = a01[e];
                    buf23[j * PITCH + c] = a23[e];
                    buf4 [j * PITCH + c] = a4[e];
                    a01[e] = 0ull; a23[e] = 0ull; a4[e] = 0.f;
                }
            }
        }
    }

    __syncthreads();

    // ================= Pass 2: horizontal rolling blur + SSIM (lane = row) =================
    {
        const int w        = tid >> 5;
        const int lane     = tid & 31;
        const int segstart = w * 30;
        const int seglen   = (w == 3) ? 28 : 30;   // 30+30+30+28 = 118
        const u64*   row01 = buf01 + lane * PITCH;
        const u64*   row23 = buf23 + lane * PITCH;
        const float* row4  = buf4  + lane * PITCH;
        const bool rowok   = (r0 + lane) < OUTW;

        u64 b01[KS], b23[KS]; float b4[KS];
        #pragma unroll
        for (int s = 0; s < KS; s++) { b01[s] = 0ull; b23[s] = 0ull; b4[s] = 0.f; }

        float acc = 0.f;

        // ---- warmup s = 0..10 ----
        #pragma unroll
        for (int s = 0; s < KS; s++) {
            int   col = segstart + s;      // <= 100, in bounds
            u64   l01 = row01[col];
            u64   l23 = row23[col];
            float l4  = row4[col];
            #pragma unroll
            for (int k = 0; k <= s; k++) {
                int d = (s - k) % KS;
                b01[d] = fma2(wp[k], l01, b01[d]);
                b23[d] = fma2(wp[k], l23, b23[d]);
                b4[d]  = fmaf(WT[k], l4, b4[d]);
            }
            if (s == KS - 1) {   // emit local out col 0 (slot 0)
                if (rowok && (c0 + segstart) < OUTW) {
                    float mux, muy;  unpack2(b01[0], mux, muy);
                    float ex2, ey2;  unpack2(b23[0], ex2, ey2);
                    float exy = b4[0];
                    float mux2 = mux * mux, muy2 = muy * muy, muxy = mux * muy;
                    float num = (2.f * muxy + 1e-4f) * (2.f * (exy - muxy) + 9e-4f);
                    float den = (mux2 + muy2 + 1e-4f) * ((ex2 - mux2) + (ey2 - muy2) + 9e-4f);
                    acc += __fdividef(num, den);
                }
                b01[0] = 0ull; b23[0] = 0ull; b4[0] = 0.f;
            }
        }

        // ---- steady s = 11..39 ----
        for (int base = KS; base < 44; base += KS) {
            #pragma unroll
            for (int ss = 0; ss < KS; ss++) {
                int s = base + ss;
                if (s < 40) {
                    int col = segstart + s;
                    if (col > IN_COLS - 1) col = IN_COLS - 1;   // clamp (guarded outputs only)
                    u64   l01 = row01[col];
                    u64   l23 = row23[col];
                    float l4  = row4[col];
                    #pragma unroll
                    for (int k = 0; k < KS; k++) {
                        int d = (ss - k + KS) % KS;
                        b01[d] = fma2(wp[k], l01, b01[d]);
                        b23[d] = fma2(wp[k], l23, b23[d]);
                        b4[d]  = fmaf(WT[k], l4, b4[d]);
                    }
                    int e  = (ss + 1) % KS;
                    int jl = s - (KS - 1);
                    if (jl < seglen && rowok && (c0 + segstart + jl) < OUTW) {
                        float mux, muy;  unpack2(b01[e], mux, muy);
                        float ex2, ey2;  unpack2(b23[e], ex2, ey2);
                        float exy = b4[e];
                        float mux2 = mux * mux, muy2 = muy * muy, muxy = mux * muy;
                        float num = (2.f * muxy + 1e-4f) * (2.f * (exy - muxy) + 9e-4f);
                        float den = (mux2 + muy2 + 1e-4f) * ((ex2 - mux2) + (ey2 - muy2) + 9e-4f);
                        acc += __fdividef(num, den);
                    }
                    b01[e] = 0ull; b23[e] = 0ull; b4[e] = 0.f;
                }
            }
        }

        // per-warp reduce -> one double atomic per warp
        #pragma unroll
        for (int off = 16; off > 0; off >>= 1)
            acc += __shfl_down_sync(0xffffffffu, acc, off);
        if (lane == 0) atomicAdd(&g_acc, (double)acc);
    }
}

extern "C" void kernel_launch(void* const* d_in, const int* in_sizes, int n_in,
                              void* d_out, int out_size) {
    const float* x = (const float*)d_in[0];
    const float* y = (const float*)d_in[1];
    float* out = (float*)d_out;

    const int smem_bytes = (2 * OUT_ROWS * PITCH * 8) + (OUT_ROWS * PITCH * 4);  // 82560
    cudaFuncSetAttribute(ssim_kernel, cudaFuncAttributeMaxDynamicSharedMemorySize, smem_bytes);

    zero_acc_kernel<<<1, 1>>>();
    dim3 grid((OUTW + OUT_COLS - 1) / OUT_COLS, (OUTW + OUT_ROWS - 1) / OUT_ROWS, NPLANE);  // 5x16x48
    ssim_kernel<<<grid, 128, smem_bytes>>>(x, y);
    finalize_kernel<<<1, 1>>>(out);
}

// round 4
// speedup vs baseline: 1.3754x; 1.3754x over previous
#include <cuda_runtime.h>

#define IMG_W    512
#define OUTW     502
#define NPLANE   48
#define IN_COLS  128
#define OUT_COLS 118
#define OUT_ROWS 32
#define IN_ROWS  42          // OUT_ROWS + 10
#define PITCH    129         // odd (u64 units) -> conflict-free strided access
#define KS       11
#define SEGL     30          // outputs per thread in pass 2 (4 segs x 30 >= 118)
#define GX       5
#define GY       16
#define NBLOCKS  (GX * GY * NPLANE)   // 3840

typedef unsigned long long u64;

__device__ double   g_acc   = 0.0;
__device__ unsigned g_count = 0u;

// Gaussian(sigma=1.5, k=11) normalized fp32 weights
static __device__ constexpr float WT[KS] = {
    0.00102838f, 0.00759876f, 0.03600077f, 0.10936069f, 0.21300554f,
    0.26601172f,
    0.21300554f, 0.10936069f, 0.03600077f, 0.00759876f, 0.00102838f
};

__device__ __forceinline__ u64 pack2(float lo, float hi) {
    u64 r; asm("mov.b64 %0,{%1,%2};" : "=l"(r) : "f"(lo), "f"(hi)); return r;
}
__device__ __forceinline__ void unpack2(u64 v, float& lo, float& hi) {
    asm("mov.b64 {%0,%1},%2;" : "=f"(lo), "=f"(hi) : "l"(v));
}
__device__ __forceinline__ u64 fma2(u64 a, u64 b, u64 c) {
    u64 r; asm("fma.rn.f32x2 %0,%1,%2,%3;" : "=l"(r) : "l"(a), "l"(b), "l"(c)); return r;
}

extern __shared__ unsigned char smem_raw[];

__launch_bounds__(128)
__global__ void ssim_kernel(const float* __restrict__ X, const float* __restrict__ Y,
                            float* __restrict__ out) {
    u64* buf01 = (u64*)smem_raw;                  // (mu_x, mu_y) after vertical blur
    u64* buf23 = buf01 + OUT_ROWS * PITCH + 8;    // (x2+y2, xy)  after vertical blur
    float* warpsums = (float*)(buf23 + OUT_ROWS * PITCH + 8);

    const int tid   = threadIdx.x;
    const int plane = blockIdx.z;
    const int c0    = blockIdx.x * OUT_COLS;
    const int r0    = blockIdx.y * OUT_ROWS;

    const float* __restrict__ xp = X + (size_t)plane * IMG_W * IMG_W;
    const float* __restrict__ yp = Y + (size_t)plane * IMG_W * IMG_W;

    u64 wp[KS];
    #pragma unroll
    for (int k = 0; k < KS; k++) wp[k] = pack2(WT[k], WT[k]);

    // ============ Pass 1: vertical sliding blur, thread = one column ============
    {
        const int  c     = tid;                       // 0..127
        const int  gc    = c0 + c;
        const bool colok = gc < IMG_W;
        const float* __restrict__ xcol = xp + gc;
        const float* __restrict__ ycol = yp + gc;

        u64 a01[KS], a23[KS];
        #pragma unroll
        for (int j = 0; j < KS; j++) { a01[j] = 0ull; a23[j] = 0ull; }

        #pragma unroll
        for (int i = 0; i < IN_ROWS; i++) {
            const int  gr = r0 + i;
            const bool ok = colok && (gr < IMG_W);
            float vx = ok ? __ldg(xcol + gr * IMG_W) : 0.f;
            float vy = ok ? __ldg(ycol + gr * IMG_W) : 0.f;
            u64 v01 = pack2(vx, vy);
            float ss = fmaf(vx, vx, vy * vy);         // x^2 + y^2
            float pp = vx * vy;                       // x*y
            u64 v23 = pack2(ss, pp);

            const int jlo = (10 - i) > 0 ? (10 - i) : 0;
            const int jhi = (IN_ROWS - 1 - i) < 10 ? (IN_ROWS - 1 - i) : 10;
            #pragma unroll
            for (int j = 0; j < KS; j++) {
                if (j >= jlo && j <= jhi) {
                    a01[j] = fma2(wp[10 - j], v01, a01[j]);
                    a23[j] = fma2(wp[10 - j], v23, a23[j]);
                }
            }
            if (i >= 10) {                            // emit output row i-10
                buf01[(i - 10) * PITCH + c] = a01[0];
                buf23[(i - 10) * PITCH + c] = a23[0];
            }
            #pragma unroll
            for (int j = 0; j < KS - 1; j++) { a01[j] = a01[j + 1]; a23[j] = a23[j + 1]; }
            a01[KS - 1] = 0ull; a23[KS - 1] = 0ull;
        }
    }

    __syncthreads();

    // ============ Pass 2: horizontal sliding blur + SSIM, thread = (row, segment) ============
    float acc = 0.f;
    {
        const int r    = tid & 31;                    // smem row
        const int seg  = tid >> 5;                    // 0..3
        const int segc = seg * SEGL;                  // first local column of segment
        const bool rowok = (r0 + r) < OUTW;
        const u64* row01 = buf01 + r * PITCH;
        const u64* row23 = buf23 + r * PITCH;

        u64 b01[KS], b23[KS];
        #pragma unroll
        for (int j = 0; j < KS; j++) { b01[j] = 0ull; b23[j] = 0ull; }

        #pragma unroll
        for (int s = 0; s < SEGL + 10; s++) {
            int col = segc + s;
            if (col > IN_COLS - 1) col = IN_COLS - 1; // clamp (feeds only dead outputs)
            u64 l01 = row01[col];
            u64 l23 = row23[col];

            const int jlo = (10 - s) > 0 ? (10 - s) : 0;
            const int jhi = (SEGL + 9 - s) < 10 ? (SEGL + 9 - s) : 10;
            #pragma unroll
            for (int j = 0; j < KS; j++) {
                if (j >= jlo && j <= jhi) {
                    b01[j] = fma2(wp[10 - j], l01, b01[j]);
                    b23[j] = fma2(wp[10 - j], l23, b23[j]);
                }
            }
            if (s >= 10) {
                const int lout = segc + (s - 10);     // local output column
                if (rowok && lout < OUT_COLS && (c0 + lout) < OUTW) {
                    float mux, muy, sxy, exy;
                    unpack2(b01[0], mux, muy);
                    unpack2(b23[0], sxy, exy);
                    float mux2 = mux * mux;
                    float muy2 = muy * muy;
                    float muxy = mux * muy;
                    float cov  = exy - muxy;
                    float t    = mux2 + muy2;
                    float A    = fmaf(2.f, muxy, 1e-4f);
                    float B    = fmaf(2.f, cov,  9e-4f);
                    float D1   = t + 1e-4f;
                    float D2   = (sxy - t) + 9e-4f;
                    acc += __fdividef(A * B, D1 * D2);
                }
            }
            #pragma unroll
            for (int j = 0; j < KS - 1; j++) { b01[j] = b01[j + 1]; b23[j] = b23[j + 1]; }
            b01[KS - 1] = 0ull; b23[KS - 1] = 0ull;
        }
    }

    // ============ Block reduce -> global atomic -> last-block finalize ============
    #pragma unroll
    for (int off = 16; off > 0; off >>= 1)
        acc += __shfl_down_sync(0xffffffffu, acc, off);
    if ((tid & 31) == 0) warpsums[tid >> 5] = acc;
    __syncthreads();
    if (tid == 0) {
        float blocksum = warpsums[0] + warpsums[1] + warpsums[2] + warpsums[3];
        atomicAdd(&g_acc, (double)blocksum);
        __threadfence();
        unsigned prev = atomicAdd(&g_count, 1u);
        if (prev == NBLOCKS - 1) {                    // last block finalizes + resets
            double total = atomicAdd(&g_acc, 0.0);    // coherent read
            const double n = (double)NPLANE * (double)OUTW * (double)OUTW;
            out[0] = (float)(1.0 - total / n);
            g_acc   = 0.0;                            // restore invariant for next replay
            g_count = 0u;
        }
    }
}

extern "C" void kernel_launch(void* const* d_in, const int* in_sizes, int n_in,
                              void* d_out, int out_size) {
    const float* x = (const float*)d_in[0];
    const float* y = (const float*)d_in[1];
    float* out = (float*)d_out;

    const int smem_bytes = 2 * (OUT_ROWS * PITCH + 8) * 8 + 64;   // ~66.3 KB
    // Unconditional every call: not a stream op, executes fine during capture,
    // and keeps kernel_launch free of static/call-count state.
    cudaFuncSetAttribute(ssim_kernel, cudaFuncAttributeMaxDynamicSharedMemorySize, smem_bytes);

    dim3 grid(GX, GY, NPLANE);   // 5 x 16 x 48 = 3840 blocks
    ssim_kernel<<<grid, 128, smem_bytes>>>(x, y, out);
}

// round 7
// speedup vs baseline: 3.1795x; 2.3117x over previous
#include <cuda_runtime.h>

#define IMG_W    512
#define OUTW     502
#define NPLANE   48
#define IN_COLS  128
#define OUT_COLS 118
#define OUT_ROWS 16
#define IN_ROWS  26          // OUT_ROWS + 10
#define PITCH    129         // u64 units; lane bank = 2r mod 32 -> phase-conflict-free
#define KS       11
#define SEGL     15          // outputs per thread in pass 2 (8 segs x 15 >= 118)
#define GX       5
#define GY       32
#define NBLOCKS  (GX * GY * NPLANE)   // 7680

typedef unsigned long long u64;

__device__ double   g_acc   = 0.0;
__device__ unsigned g_count = 0u;

// Gaussian(sigma=1.5, k=11) normalized fp32 weights
static __device__ constexpr float WT[KS] = {
    0.00102838f, 0.00759876f, 0.03600077f, 0.10936069f, 0.21300554f,
    0.26601172f,
    0.21300554f, 0.10936069f, 0.03600077f, 0.00759876f, 0.00102838f
};

__device__ __forceinline__ u64 pack2(float lo, float hi) {
    u64 r; asm("mov.b64 %0,{%1,%2};" : "=l"(r) : "f"(lo), "f"(hi)); return r;
}
__device__ __forceinline__ void unpack2(u64 v, float& lo, float& hi) {
    asm("mov.b64 {%0,%1},%2;" : "=f"(lo), "=f"(hi) : "l"(v));
}
__device__ __forceinline__ u64 fma2(u64 a, u64 b, u64 c) {
    u64 r; asm("fma.rn.f32x2 %0,%1,%2,%3;" : "=l"(r) : "l"(a), "l"(b), "l"(c)); return r;
}

extern __shared__ unsigned char smem_raw[];

__launch_bounds__(128)
__global__ void ssim_kernel(const float* __restrict__ X, const float* __restrict__ Y,
                            float* __restrict__ out) {
    u64* buf01 = (u64*)smem_raw;                  // (mu_x, mu_y) after vertical blur
    u64* buf23 = buf01 + OUT_ROWS * PITCH + 8;    // (x2+y2, xy)  after vertical blur
    float* warpsums = (float*)(buf23 + OUT_ROWS * PITCH + 8);

    const int tid   = threadIdx.x;
    const int plane = blockIdx.z;
    const int c0    = blockIdx.x * OUT_COLS;
    const int r0    = blockIdx.y * OUT_ROWS;

    const float* __restrict__ xp = X + (size_t)plane * IMG_W * IMG_W;
    const float* __restrict__ yp = Y + (size_t)plane * IMG_W * IMG_W;

    u64 wp[KS];
    #pragma unroll
    for (int k = 0; k < KS; k++) wp[k] = pack2(WT[k], WT[k]);

    // ============ Pass 1: vertical sliding blur, thread = one column ============
    {
        const int  c     = tid;                       // 0..127
        const int  gc    = c0 + c;
        const bool colok = gc < IMG_W;
        const float* __restrict__ xcol = xp + gc;
        const float* __restrict__ ycol = yp + gc;

        u64 a01[KS], a23[KS];
        #pragma unroll
        for (int j = 0; j < KS; j++) { a01[j] = 0ull; a23[j] = 0ull; }

        #pragma unroll
        for (int i = 0; i < IN_ROWS; i++) {
            const int  gr = r0 + i;
            const bool ok = colok && (gr < IMG_W);
            float vx = ok ? __ldg(xcol + gr * IMG_W) : 0.f;
            float vy = ok ? __ldg(ycol + gr * IMG_W) : 0.f;
            u64 v01 = pack2(vx, vy);
            float ss = fmaf(vx, vx, vy * vy);         // x^2 + y^2
            float pp = vx * vy;                       // x*y
            u64 v23 = pack2(ss, pp);

            const int jlo = (10 - i) > 0 ? (10 - i) : 0;
            const int jhi = (IN_ROWS - 1 - i) < 10 ? (IN_ROWS - 1 - i) : 10;
            #pragma unroll
            for (int j = 0; j < KS; j++) {
                if (j >= jlo && j <= jhi) {
                    a01[j] = fma2(wp[10 - j], v01, a01[j]);
                    a23[j] = fma2(wp[10 - j], v23, a23[j]);
                }
            }
            if (i >= 10) {                            // emit output row i-10
                buf01[(i - 10) * PITCH + c] = a01[0];
                buf23[(i - 10) * PITCH + c] = a23[0];
            }
            #pragma unroll
            for (int j = 0; j < KS - 1; j++) { a01[j] = a01[j + 1]; a23[j] = a23[j + 1]; }
            a01[KS - 1] = 0ull; a23[KS - 1] = 0ull;
        }
    }

    __syncthreads();

    // ============ Pass 2: horizontal sliding blur + SSIM, thread = (row, segment) ============
    float acc = 0.f;
    {
        const int r    = tid & 15;                    // smem row (0..15)
        const int seg  = tid >> 4;                    // 0..7
        const int segc = seg * SEGL;                  // first local column of segment
        const bool rowok = (r0 + r) < OUTW;
        const u64* row01 = buf01 + r * PITCH;
        const u64* row23 = buf23 + r * PITCH;

        u64 b01[KS], b23[KS];
        #pragma unroll
        for (int j = 0; j < KS; j++) { b01[j] = 0ull; b23[j] = 0ull; }

        #pragma unroll
        for (int s = 0; s < SEGL + 10; s++) {
            int col = segc + s;
            if (col > IN_COLS - 1) col = IN_COLS - 1; // clamp (feeds only dead outputs)
            u64 l01 = row01[col];
            u64 l23 = row23[col];

            const int jlo = (10 - s) > 0 ? (10 - s) : 0;
            const int jhi = (SEGL + 9 - s) < 10 ? (SEGL + 9 - s) : 10;
            #pragma unroll
            for (int j = 0; j < KS; j++) {
                if (j >= jlo && j <= jhi) {
                    b01[j] = fma2(wp[10 - j], l01, b01[j]);
                    b23[j] = fma2(wp[10 - j], l23, b23[j]);
                }
            }
            if (s >= 10) {
                const int lout = segc + (s - 10);     // local output column
                if (rowok && lout < OUT_COLS && (c0 + lout) < OUTW) {
                    float mux, muy, sxy, exy;
                    unpack2(b01[0], mux, muy);
                    unpack2(b23[0], sxy, exy);
                    float mux2 = mux * mux;
                    float muy2 = muy * muy;
                    float muxy = mux * muy;
                    float cov  = exy - muxy;
                    float t    = mux2 + muy2;
                    float A    = fmaf(2.f, muxy, 1e-4f);
                    float B    = fmaf(2.f, cov,  9e-4f);
                    float D1   = t + 1e-4f;
                    float D2   = (sxy - t) + 9e-4f;
                    acc += __fdividef(A * B, D1 * D2);
                }
            }
            #pragma unroll
            for (int j = 0; j < KS - 1; j++) { b01[j] = b01[j + 1]; b23[j] = b23[j + 1]; }
            b01[KS - 1] = 0ull; b23[KS - 1] = 0ull;
        }
    }

    // ============ Block reduce -> global atomic -> last-block finalize ============
    #pragma unroll
    for (int off = 16; off > 0; off >>= 1)
        acc += __shfl_down_sync(0xffffffffu, acc, off);
    if ((tid & 31) == 0) warpsums[tid >> 5] = acc;
    __syncthreads();
    if (tid == 0) {
        float blocksum = warpsums[0] + warpsums[1] + warpsums[2] + warpsums[3];
        atomicAdd(&g_acc, (double)blocksum);
        __threadfence();
        unsigned prev = atomicAdd(&g_count, 1u);
        if (prev == NBLOCKS - 1) {                    // last block finalizes + resets
            double total = atomicAdd(&g_acc, 0.0);    // coherent read
            const double n = (double)NPLANE * (double)OUTW * (double)OUTW;
            out[0] = (float)(1.0 - total / n);
            g_acc   = 0.0;                            // restore invariant for next replay
            g_count = 0u;
        }
    }
}

extern "C" void kernel_launch(void* const* d_in, const int* in_sizes, int n_in,
                              void* d_out, int out_size) {
    const float* x = (const float*)d_in[0];
    const float* y = (const float*)d_in[1];
    float* out = (float*)d_out;

    const int smem_bytes = 2 * (OUT_ROWS * PITCH + 8) * 8 + 64;   // ~33.3 KB
    cudaFuncSetAttribute(ssim_kernel, cudaFuncAttributeMaxDynamicSharedMemorySize, smem_bytes);

    dim3 grid(GX, GY, NPLANE);   // 5 x 32 x 48 = 7680 blocks
    ssim_kernel<<<grid, 128, smem_bytes>>>(x, y, out);
}